// round 6
// baseline (speedup 1.0000x reference)
#include <cuda_runtime.h>

// ----------------------------------------------------------------------------
// MultiHeadAttention, fp32.
// Stage 1/3: 128x128x16 SGEMM (8x8 micro-tile).  [unchanged from R5 - validated]
// Stage 2: flash attention Br=128, Bc=64, 8x4 micro-tile, 64KB smem,
//          GEMM2 split into two 64-row halves so P aliases Kt (16KB).
// ----------------------------------------------------------------------------

constexpr int BATCH = 2;
constexpr int SEQ   = 2048;
constexpr int DM    = 768;
constexpr int NH    = 12;
constexpr int HD    = 64;
constexpr int BH    = BATCH * NH;   // 24
constexpr int MTOT  = BATCH * SEQ;  // 4096
constexpr int NTILES = SEQ / 64;    // 32
constexpr float NEGV  = -10000.0f;
constexpr float SCALE = 0.125f;     // 1/sqrt(64), exact power of 2

__device__ float g_Q[BATCH * NH * SEQ * HD];
__device__ float g_K[BATCH * NH * SEQ * HD];
__device__ float g_V[BATCH * NH * SEQ * HD];
__device__ float g_O[BATCH * NH * SEQ * HD];

// ----------------------------------------------------------------------------
// Stage 1: QKV projections. 128x128 tile, BK=16, 256 threads, 8x8 per thread.
// ----------------------------------------------------------------------------
__global__ void __launch_bounds__(256) qkv_proj_kernel(
    const float* __restrict__ q, const float* __restrict__ k, const float* __restrict__ v,
    const float* __restrict__ Wq, const float* __restrict__ Wk, const float* __restrict__ Wv)
{
    __shared__ float As[16 * 128];   // As[k][m]
    __shared__ float Bs[16 * 128];   // Bs[k][n]

    const int z = blockIdx.z;
    const float* X = (z == 0) ? q : (z == 1) ? k : v;
    const float* W = (z == 0) ? Wq : (z == 1) ? Wk : Wv;
    float* out = (z == 0) ? g_Q : (z == 1) ? g_K : g_V;

    const int n0 = blockIdx.x * 128;
    const int m0 = blockIdx.y * 128;
    const int tid = threadIdx.x;
    const int tx = tid & 15, ty = tid >> 4;

    const int am = tid >> 1;
    const int ak = (tid & 1) * 8;
    const int kb = tid >> 5;
    const int nb = (tid & 31) * 4;

    float acc[8][8] = {};

    for (int k0 = 0; k0 < DM; k0 += 16) {
        float4 a0 = *reinterpret_cast<const float4*>(&X[(size_t)(m0 + am) * DM + k0 + ak]);
        float4 a1 = *reinterpret_cast<const float4*>(&X[(size_t)(m0 + am) * DM + k0 + ak + 4]);
        As[(ak + 0) * 128 + am] = a0.x;
        As[(ak + 1) * 128 + am] = a0.y;
        As[(ak + 2) * 128 + am] = a0.z;
        As[(ak + 3) * 128 + am] = a0.w;
        As[(ak + 4) * 128 + am] = a1.x;
        As[(ak + 5) * 128 + am] = a1.y;
        As[(ak + 6) * 128 + am] = a1.z;
        As[(ak + 7) * 128 + am] = a1.w;
        float4 b0 = *reinterpret_cast<const float4*>(&W[(size_t)(k0 + kb) * DM + n0 + nb]);
        float4 b1 = *reinterpret_cast<const float4*>(&W[(size_t)(k0 + kb + 8) * DM + n0 + nb]);
        *reinterpret_cast<float4*>(&Bs[kb * 128 + nb]) = b0;
        *reinterpret_cast<float4*>(&Bs[(kb + 8) * 128 + nb]) = b1;
        __syncthreads();

        #pragma unroll
        for (int kk = 0; kk < 16; ++kk) {
            float4 ra0 = *reinterpret_cast<float4*>(&As[kk * 128 + ty * 8]);
            float4 ra1 = *reinterpret_cast<float4*>(&As[kk * 128 + ty * 8 + 4]);
            float4 rb0 = *reinterpret_cast<float4*>(&Bs[kk * 128 + tx * 8]);
            float4 rb1 = *reinterpret_cast<float4*>(&Bs[kk * 128 + tx * 8 + 4]);
            float ar[8] = {ra0.x, ra0.y, ra0.z, ra0.w, ra1.x, ra1.y, ra1.z, ra1.w};
            float br[8] = {rb0.x, rb0.y, rb0.z, rb0.w, rb1.x, rb1.y, rb1.z, rb1.w};
            #pragma unroll
            for (int i = 0; i < 8; ++i)
                #pragma unroll
                for (int j = 0; j < 8; ++j)
                    acc[i][j] += ar[i] * br[j];
        }
        __syncthreads();
    }

    const int ncol = n0 + tx * 8;
    const int head = ncol >> 6;
    const int d0   = ncol & 63;
    #pragma unroll
    for (int i = 0; i < 8; ++i) {
        int m = m0 + ty * 8 + i;
        int b = m >> 11;
        int s = m & (SEQ - 1);
        float* dst = &out[(((size_t)(b * NH + head)) * SEQ + s) * HD + d0];
        *reinterpret_cast<float4*>(dst)     = make_float4(acc[i][0], acc[i][1], acc[i][2], acc[i][3]);
        *reinterpret_cast<float4*>(dst + 4) = make_float4(acc[i][4], acc[i][5], acc[i][6], acc[i][7]);
    }
}

// ----------------------------------------------------------------------------
// Stage 2: flash attention.  grid = (SEQ/128, B*H), 256 threads, 64KB smem.
// Qt[64][128] (pre-scaled), Kt[64][64] (aliased as Ps), Vs[64][64].
// Thread (tx,ty): cols cc..cc+3, rows rr..rr+3 (half0) and rr+64.. (half1).
// ----------------------------------------------------------------------------
__global__ void __launch_bounds__(256) flash_kernel(
    const int* __restrict__ attn_mask, const int* __restrict__ mask_future)
{
    extern __shared__ float sm[];
    float* Qt = sm;                 // [64 d][128 row]
    float* Kt = sm + 8192;          // [64 d][64 col]; aliased as Ps[64][64]
    float* Vs = sm + 12288;         // [64 row][64 d]
    float* Ps = Kt;

    const int tid = threadIdx.x;
    const int tx = tid & 15, ty = tid >> 4;
    const int rr = ty * 4, cc = tx * 4;
    const int qt = blockIdx.x;
    const int bh = blockIdx.y;
    const int b  = bh / NH;
    const int q0 = qt * 128;
    const bool causal = (mask_future[0] != 0);

    // load Q tile transposed, pre-scaled by 1/8 (exact): Qt[d][row]
    {
        int j = tid & 127;
        int dbase = (tid >> 7) * 32;
        #pragma unroll
        for (int qd = 0; qd < 8; ++qd) {
            int d = dbase + qd * 4;
            float4 qv = *reinterpret_cast<const float4*>(
                &g_Q[(((size_t)bh) * SEQ + q0 + j) * HD + d]);
            Qt[(d + 0) * 128 + j] = qv.x * SCALE;
            Qt[(d + 1) * 128 + j] = qv.y * SCALE;
            Qt[(d + 2) * 128 + j] = qv.z * SCALE;
            Qt[(d + 3) * 128 + j] = qv.w * SCALE;
        }
    }

    float m0[4], l0[4], o0[4][4];
    float m1[4], l1[4], o1[4][4];
    #pragma unroll
    for (int i = 0; i < 4; ++i) {
        m0[i] = -1e30f; l0[i] = 0.0f;
        m1[i] = -1e30f; l1[i] = 0.0f;
        #pragma unroll
        for (int j = 0; j < 4; ++j) { o0[i][j] = 0.0f; o1[i][j] = 0.0f; }
    }

    // causal limit: tiles covering keys <= q0+127 -> 2*qt+2 tiles of 64.
    // Reference softmax spans ALL keys; rows with zero valid visible keys
    // must extend over future tiles (checked after the diagonal tile).
    int limit = causal ? (2 * qt + 2) : NTILES;

    for (int kt = 0; kt < NTILES; ++kt) {
        if (kt >= limit) break;
        const int k0 = kt * 64;
        __syncthreads();  // prior GEMM2/half1 reads done before overwriting Kt/Vs

        // K tile -> transposed smem
        {
            int j = tid & 63;
            int dq = (tid >> 6) * 16;
            #pragma unroll
            for (int qd = 0; qd < 4; ++qd) {
                int d = dq + qd * 4;
                float4 kv = *reinterpret_cast<const float4*>(
                    &g_K[(((size_t)bh) * SEQ + k0 + j) * HD + d]);
                Kt[(d + 0) * 64 + j] = kv.x;
                Kt[(d + 1) * 64 + j] = kv.y;
                Kt[(d + 2) * 64 + j] = kv.z;
                Kt[(d + 3) * 64 + j] = kv.w;
            }
        }
        // V tile (row-major)
        #pragma unroll
        for (int qd = 0; qd < 4; ++qd) {
            int fi = tid + qd * 256;
            int row = fi >> 4;
            int col = (fi & 15) * 4;
            *reinterpret_cast<float4*>(&Vs[row * 64 + col]) =
                *reinterpret_cast<const float4*>(&g_V[(((size_t)bh) * SEQ + k0 + row) * HD + col]);
        }
        int mk[4];
        #pragma unroll
        for (int j = 0; j < 4; ++j)
            mk[j] = attn_mask[b * SEQ + k0 + cc + j];
        __syncthreads();

        // GEMM1: S = (Q*s) K^T for both halves (8x4 per thread)
        float s0[4][4] = {}, s1[4][4] = {};
        #pragma unroll 16
        for (int d = 0; d < 64; ++d) {
            float4 qa = *reinterpret_cast<float4*>(&Qt[d * 128 + rr]);
            float4 qb = *reinterpret_cast<float4*>(&Qt[d * 128 + 64 + rr]);
            float4 kb = *reinterpret_cast<float4*>(&Kt[d * 64 + cc]);
            s0[0][0] += qa.x * kb.x; s0[0][1] += qa.x * kb.y; s0[0][2] += qa.x * kb.z; s0[0][3] += qa.x * kb.w;
            s0[1][0] += qa.y * kb.x; s0[1][1] += qa.y * kb.y; s0[1][2] += qa.y * kb.z; s0[1][3] += qa.y * kb.w;
            s0[2][0] += qa.z * kb.x; s0[2][1] += qa.z * kb.y; s0[2][2] += qa.z * kb.z; s0[2][3] += qa.z * kb.w;
            s0[3][0] += qa.w * kb.x; s0[3][1] += qa.w * kb.y; s0[3][2] += qa.w * kb.z; s0[3][3] += qa.w * kb.w;
            s1[0][0] += qb.x * kb.x; s1[0][1] += qb.x * kb.y; s1[0][2] += qb.x * kb.z; s1[0][3] += qb.x * kb.w;
            s1[1][0] += qb.y * kb.x; s1[1][1] += qb.y * kb.y; s1[1][2] += qb.y * kb.z; s1[1][3] += qb.y * kb.w;
            s1[2][0] += qb.z * kb.x; s1[2][1] += qb.z * kb.y; s1[2][2] += qb.z * kb.z; s1[2][3] += qb.z * kb.w;
            s1[3][0] += qb.w * kb.x; s1[3][1] += qb.w * kb.y; s1[3][2] += qb.w * kb.z; s1[3][3] += qb.w * kb.w;
        }

        // masks (scores already scaled; causal ADDS, padding SETS) + softmax
        #pragma unroll
        for (int i = 0; i < 4; ++i) {
            int ig0 = q0 + rr + i;
            int ig1 = ig0 + 64;
            #pragma unroll
            for (int j = 0; j < 4; ++j) {
                int jg = k0 + cc + j;
                float v0 = s0[i][j];
                float v1 = s1[i][j];
                if (causal && jg > ig0) v0 += NEGV;
                if (causal && jg > ig1) v1 += NEGV;
                if (mk[j] == 0) { v0 = NEGV; v1 = NEGV; }
                s0[i][j] = v0;
                s1[i][j] = v1;
            }
        }
        #pragma unroll
        for (int i = 0; i < 4; ++i) {
            // half0
            float tm = fmaxf(fmaxf(s0[i][0], s0[i][1]), fmaxf(s0[i][2], s0[i][3]));
            #pragma unroll
            for (int off = 8; off; off >>= 1)
                tm = fmaxf(tm, __shfl_xor_sync(0xffffffffu, tm, off));
            float mnew = fmaxf(m0[i], tm);
            float alpha = __expf(m0[i] - mnew);
            float ps = 0.0f;
            #pragma unroll
            for (int j = 0; j < 4; ++j) {
                float p = __expf(s0[i][j] - mnew);
                s0[i][j] = p;
                ps += p;
            }
            #pragma unroll
            for (int off = 8; off; off >>= 1)
                ps += __shfl_xor_sync(0xffffffffu, ps, off);
            l0[i] = l0[i] * alpha + ps;
            m0[i] = mnew;
            o0[i][0] *= alpha; o0[i][1] *= alpha; o0[i][2] *= alpha; o0[i][3] *= alpha;
            // half1
            float tm1 = fmaxf(fmaxf(s1[i][0], s1[i][1]), fmaxf(s1[i][2], s1[i][3]));
            #pragma unroll
            for (int off = 8; off; off >>= 1)
                tm1 = fmaxf(tm1, __shfl_xor_sync(0xffffffffu, tm1, off));
            float mnew1 = fmaxf(m1[i], tm1);
            float alpha1 = __expf(m1[i] - mnew1);
            float ps1 = 0.0f;
            #pragma unroll
            for (int j = 0; j < 4; ++j) {
                float p = __expf(s1[i][j] - mnew1);
                s1[i][j] = p;
                ps1 += p;
            }
            #pragma unroll
            for (int off = 8; off; off >>= 1)
                ps1 += __shfl_xor_sync(0xffffffffu, ps1, off);
            l1[i] = l1[i] * alpha1 + ps1;
            m1[i] = mnew1;
            o1[i][0] *= alpha1; o1[i][1] *= alpha1; o1[i][2] *= alpha1; o1[i][3] *= alpha1;
        }

        __syncthreads();  // all GEMM1 Kt reads done before Ps(=Kt) writes

        // half0: write P, GEMM2
        #pragma unroll
        for (int i = 0; i < 4; ++i)
            *reinterpret_cast<float4*>(&Ps[(rr + i) * 64 + cc]) =
                make_float4(s0[i][0], s0[i][1], s0[i][2], s0[i][3]);
        __syncthreads();
        #pragma unroll 16
        for (int j = 0; j < 64; ++j) {
            float a0 = Ps[(rr + 0) * 64 + j];
            float a1 = Ps[(rr + 1) * 64 + j];
            float a2 = Ps[(rr + 2) * 64 + j];
            float a3 = Ps[(rr + 3) * 64 + j];
            float4 vv = *reinterpret_cast<float4*>(&Vs[j * 64 + cc]);
            o0[0][0] += a0 * vv.x; o0[0][1] += a0 * vv.y; o0[0][2] += a0 * vv.z; o0[0][3] += a0 * vv.w;
            o0[1][0] += a1 * vv.x; o0[1][1] += a1 * vv.y; o0[1][2] += a1 * vv.z; o0[1][3] += a1 * vv.w;
            o0[2][0] += a2 * vv.x; o0[2][1] += a2 * vv.y; o0[2][2] += a2 * vv.z; o0[2][3] += a2 * vv.w;
            o0[3][0] += a3 * vv.x; o0[3][1] += a3 * vv.y; o0[3][2] += a3 * vv.z; o0[3][3] += a3 * vv.w;
        }
        __syncthreads();

        // half1: write P, GEMM2
        #pragma unroll
        for (int i = 0; i < 4; ++i)
            *reinterpret_cast<float4*>(&Ps[(rr + i) * 64 + cc]) =
                make_float4(s1[i][0], s1[i][1], s1[i][2], s1[i][3]);
        __syncthreads();
        #pragma unroll 16
        for (int j = 0; j < 64; ++j) {
            float a0 = Ps[(rr + 0) * 64 + j];
            float a1 = Ps[(rr + 1) * 64 + j];
            float a2 = Ps[(rr + 2) * 64 + j];
            float a3 = Ps[(rr + 3) * 64 + j];
            float4 vv = *reinterpret_cast<float4*>(&Vs[j * 64 + cc]);
            o1[0][0] += a0 * vv.x; o1[0][1] += a0 * vv.y; o1[0][2] += a0 * vv.z; o1[0][3] += a0 * vv.w;
            o1[1][0] += a1 * vv.x; o1[1][1] += a1 * vv.y; o1[1][2] += a1 * vv.z; o1[1][3] += a1 * vv.w;
            o1[2][0] += a2 * vv.x; o1[2][1] += a2 * vv.y; o1[2][2] += a2 * vv.z; o1[2][3] += a2 * vv.w;
            o1[3][0] += a3 * vv.x; o1[3][1] += a3 * vv.y; o1[3][2] += a3 * vv.z; o1[3][3] += a3 * vv.w;
        }

        // after the last causal tile: any row with zero valid visible keys
        // (m == -1e4 exactly) must attend to future keys (reference semantics)
        if (causal && kt == limit - 1 && limit != NTILES) {
            int lack = 0;
            #pragma unroll
            for (int i = 0; i < 4; ++i) {
                if (m0[i] <= -5000.0f) lack = 1;
                if (m1[i] <= -5000.0f) lack = 1;
            }
            if (__syncthreads_or(lack)) limit = NTILES;
        }
    }

    // epilogue
    #pragma unroll
    for (int i = 0; i < 4; ++i) {
        float inv0 = 1.0f / l0[i];
        float inv1 = 1.0f / l1[i];
        *reinterpret_cast<float4*>(&g_O[(((size_t)bh) * SEQ + q0 + rr + i) * HD + cc]) =
            make_float4(o0[i][0] * inv0, o0[i][1] * inv0, o0[i][2] * inv0, o0[i][3] * inv0);
        *reinterpret_cast<float4*>(&g_O[(((size_t)bh) * SEQ + q0 + 64 + rr + i) * HD + cc]) =
            make_float4(o1[i][0] * inv1, o1[i][1] * inv1, o1[i][2] * inv1, o1[i][3] * inv1);
    }
}

// ----------------------------------------------------------------------------
// Stage 3: output projection. 128x128x16 SGEMM; A gathered head-major.
// ----------------------------------------------------------------------------
__global__ void __launch_bounds__(256) out_proj_kernel(
    const float* __restrict__ Wo, float* __restrict__ out)
{
    __shared__ float As[16 * 128];
    __shared__ float Bs[16 * 128];

    const int n0 = blockIdx.x * 128;
    const int m0 = blockIdx.y * 128;
    const int tid = threadIdx.x;
    const int tx = tid & 15, ty = tid >> 4;

    const int am = tid >> 1;
    const int ak = (tid & 1) * 8;
    const int kb = tid >> 5;
    const int nb = (tid & 31) * 4;

    const int m = m0 + am;
    const int bb = m >> 11;
    const int ss = m & (SEQ - 1);

    float acc[8][8] = {};

    for (int k0 = 0; k0 < DM; k0 += 16) {
        int kidx = k0 + ak;
        int h = kidx >> 6, dd = kidx & 63;
        const float* src = &g_O[(((size_t)(bb * NH + h)) * SEQ + ss) * HD + dd];
        float4 a0 = *reinterpret_cast<const float4*>(src);
        float4 a1 = *reinterpret_cast<const float4*>(src + 4);
        As[(ak + 0) * 128 + am] = a0.x;
        As[(ak + 1) * 128 + am] = a0.y;
        As[(ak + 2) * 128 + am] = a0.z;
        As[(ak + 3) * 128 + am] = a0.w;
        As[(ak + 4) * 128 + am] = a1.x;
        As[(ak + 5) * 128 + am] = a1.y;
        As[(ak + 6) * 128 + am] = a1.z;
        As[(ak + 7) * 128 + am] = a1.w;
        float4 b0 = *reinterpret_cast<const float4*>(&Wo[(size_t)(k0 + kb) * DM + n0 + nb]);
        float4 b1 = *reinterpret_cast<const float4*>(&Wo[(size_t)(k0 + kb + 8) * DM + n0 + nb]);
        *reinterpret_cast<float4*>(&Bs[kb * 128 + nb]) = b0;
        *reinterpret_cast<float4*>(&Bs[(kb + 8) * 128 + nb]) = b1;
        __syncthreads();

        #pragma unroll
        for (int kk = 0; kk < 16; ++kk) {
            float4 ra0 = *reinterpret_cast<float4*>(&As[kk * 128 + ty * 8]);
            float4 ra1 = *reinterpret_cast<float4*>(&As[kk * 128 + ty * 8 + 4]);
            float4 rb0 = *reinterpret_cast<float4*>(&Bs[kk * 128 + tx * 8]);
            float4 rb1 = *reinterpret_cast<float4*>(&Bs[kk * 128 + tx * 8 + 4]);
            float ar[8] = {ra0.x, ra0.y, ra0.z, ra0.w, ra1.x, ra1.y, ra1.z, ra1.w};
            float br[8] = {rb0.x, rb0.y, rb0.z, rb0.w, rb1.x, rb1.y, rb1.z, rb1.w};
            #pragma unroll
            for (int i = 0; i < 8; ++i)
                #pragma unroll
                for (int j = 0; j < 8; ++j)
                    acc[i][j] += ar[i] * br[j];
        }
        __syncthreads();
    }

    #pragma unroll
    for (int i = 0; i < 8; ++i) {
        int mm = m0 + ty * 8 + i;
        float* dst = &out[(size_t)mm * DM + n0 + tx * 8];
        *reinterpret_cast<float4*>(dst)     = make_float4(acc[i][0], acc[i][1], acc[i][2], acc[i][3]);
        *reinterpret_cast<float4*>(dst + 4) = make_float4(acc[i][4], acc[i][5], acc[i][6], acc[i][7]);
    }
}

// ----------------------------------------------------------------------------
extern "C" void kernel_launch(void* const* d_in, const int* in_sizes, int n_in,
                              void* d_out, int out_size)
{
    const float* q    = (const float*)d_in[0];
    const float* k    = (const float*)d_in[1];
    const float* v    = (const float*)d_in[2];
    const int*   mask = (const int*)d_in[3];
    const float* Wq   = (const float*)d_in[4];
    const float* Wk   = (const float*)d_in[5];
    const float* Wv   = (const float*)d_in[6];
    const float* Wo   = (const float*)d_in[7];
    const int*   mfut = (const int*)d_in[8];
    float* out = (float*)d_out;

    const int flash_smem = 16384 * (int)sizeof(float);  // 64KB
    static bool attr_set = false;
    if (!attr_set) {
        cudaFuncSetAttribute(flash_kernel, cudaFuncAttributeMaxDynamicSharedMemorySize, flash_smem);
        attr_set = true;
    }

    qkv_proj_kernel<<<dim3(DM / 128, MTOT / 128, 3), 256>>>(q, k, v, Wq, Wk, Wv);
    flash_kernel<<<dim3(SEQ / 128, BH), 256, flash_smem>>>(mask, mfut);
    out_proj_kernel<<<dim3(DM / 128, MTOT / 128), 256>>>(Wo, out);
}